// round 9
// baseline (speedup 1.0000x reference)
#include <cuda_runtime.h>
#include <math.h>

#define BB 4
#define NN 4096
#define DD 1024
#define FF 64
#define MROWS (BB*NN)      // 16384
#define HID (4*DD)         // 4096

// ---------------- scratch (static __device__ — no allocation allowed) -------
__device__ float g_xn[(size_t)MROWS*DD];
__device__ float g_q [(size_t)MROWS*FF];
__device__ float g_k [(size_t)MROWS*FF];
__device__ float g_v [(size_t)MROWS*DD];
__device__ float g_attn[(size_t)MROWS*DD];
__device__ float g_y1[(size_t)MROWS*DD];
__device__ float g_h [(size_t)MROWS*DD];
__device__ float g_hf[(size_t)MROWS*HID];

// ---------------- LayerNorm: one CTA per row of 1024 ------------------------
__global__ void ln_kernel(const float* __restrict__ x, const float* __restrict__ w,
                          const float* __restrict__ b, float* __restrict__ y) {
    int row = blockIdx.x;
    int t = threadIdx.x;                      // 256 threads, 1 float4 each
    const float4* xr = (const float4*)(x + (size_t)row * DD);
    float4 p = xr[t];
    float s  = p.x + p.y + p.z + p.w;
    float ss = p.x*p.x + p.y*p.y + p.z*p.z + p.w*p.w;
    #pragma unroll
    for (int o = 16; o; o >>= 1) {
        s  += __shfl_down_sync(0xffffffffu, s,  o);
        ss += __shfl_down_sync(0xffffffffu, ss, o);
    }
    __shared__ float rs[8], rss[8];
    int wid = t >> 5, lid = t & 31;
    if (lid == 0) { rs[wid] = s; rss[wid] = ss; }
    __syncthreads();
    float tot = 0.f, tot2 = 0.f;
    #pragma unroll
    for (int i = 0; i < 8; i++) { tot += rs[i]; tot2 += rss[i]; }
    float mu  = tot * (1.0f / DD);
    float var = tot2 * (1.0f / DD) - mu * mu;
    float inv = rsqrtf(var + 1e-5f);
    float4 wv = ((const float4*)w)[t];
    float4 bv = ((const float4*)b)[t];
    float4 o;
    o.x = (p.x - mu) * inv * wv.x + bv.x;
    o.y = (p.y - mu) * inv * wv.y + bv.y;
    o.z = (p.z - mu) * inv * wv.z + bv.z;
    o.w = (p.w - mu) * inv * wv.w + bv.w;
    ((float4*)(y + (size_t)row * DD))[t] = o;
}

// ---------------- GEMM: C[M,N] = A[M,K] @ W[N,K]^T + bias, with epilogue ----
// EPI: 0 = none, 1 = elu(x)+1, 2 = gelu exact, 3 = residual add
template<int EPI>
__global__ void gemm_tn(const float* __restrict__ A, const float* __restrict__ W,
                        const float* __restrict__ bias, const float* __restrict__ R,
                        float* __restrict__ C, int M, int Nout, int Kd) {
    __shared__ float As[16][68];   // [k][m], padded
    __shared__ float Ws[16][68];   // [k][n], padded
    int t  = threadIdx.x;
    int tx = t & 15, ty = t >> 4;
    int m0 = blockIdx.y * 64, n0 = blockIdx.x * 64;
    int lr = t >> 2;            // 0..63
    int lc = (t & 3) * 4;       // 0,4,8,12
    const float* Ag = A + (size_t)(m0 + lr) * Kd + lc;
    const float* Wg = W + (size_t)(n0 + lr) * Kd + lc;

    float acc[4][4];
    #pragma unroll
    for (int i = 0; i < 4; i++)
        #pragma unroll
        for (int j = 0; j < 4; j++) acc[i][j] = 0.f;

    for (int k0 = 0; k0 < Kd; k0 += 16) {
        float4 av = *(const float4*)(Ag + k0);
        float4 wv = *(const float4*)(Wg + k0);
        As[lc+0][lr] = av.x; As[lc+1][lr] = av.y;
        As[lc+2][lr] = av.z; As[lc+3][lr] = av.w;
        Ws[lc+0][lr] = wv.x; Ws[lc+1][lr] = wv.y;
        Ws[lc+2][lr] = wv.z; Ws[lc+3][lr] = wv.w;
        __syncthreads();
        #pragma unroll
        for (int kk = 0; kk < 16; kk++) {
            float4 a = *(const float4*)&As[kk][ty * 4];
            float4 b = *(const float4*)&Ws[kk][tx * 4];
            acc[0][0] += a.x*b.x; acc[0][1] += a.x*b.y; acc[0][2] += a.x*b.z; acc[0][3] += a.x*b.w;
            acc[1][0] += a.y*b.x; acc[1][1] += a.y*b.y; acc[1][2] += a.y*b.z; acc[1][3] += a.y*b.w;
            acc[2][0] += a.z*b.x; acc[2][1] += a.z*b.y; acc[2][2] += a.z*b.z; acc[2][3] += a.z*b.w;
            acc[3][0] += a.w*b.x; acc[3][1] += a.w*b.y; acc[3][2] += a.w*b.z; acc[3][3] += a.w*b.w;
        }
        __syncthreads();
    }

    #pragma unroll
    for (int i = 0; i < 4; i++) {
        int m = m0 + ty * 4 + i;
        #pragma unroll
        for (int j = 0; j < 4; j++) {
            int n = n0 + tx * 4 + j;
            float v = acc[i][j] + bias[n];
            if (EPI == 1) v = (v > 0.f) ? (v + 1.f) : expf(v);               // elu+1
            else if (EPI == 2) v = 0.5f * v * (1.f + erff(v * 0.70710678118f)); // gelu exact
            else if (EPI == 3) v += R[(size_t)m * Nout + n];                 // residual
            C[(size_t)m * Nout + n] = v;
        }
    }
}

// ---------------- causal linear attention scan -------------------------------
// grid: (D/128, B), 128 threads. Each thread owns one output dim d, holds
// KV[f=0..63][d] in registers. Exact replay of the reference recurrence.
__global__ void attn_scan(const float* __restrict__ Q, const float* __restrict__ K,
                          const float* __restrict__ V, float* __restrict__ O) {
    int b = blockIdx.y;
    int t = threadIdx.x;
    int d = blockIdx.x * 128 + t;
    __shared__ float qs[64], ks[64], Kss[64];
    if (t < 64) Kss[t] = 0.f;
    float kv[64];
    #pragma unroll
    for (int f = 0; f < 64; f++) kv[f] = 0.f;

    const float* Qb = Q + (size_t)b * NN * FF;
    const float* Kb = K + (size_t)b * NN * FF;
    const float* Vb = V + (size_t)b * NN * DD + d;
    float*       Ob = O + (size_t)b * NN * DD + d;

    for (int i = 0; i < NN; i++) {
        if (t < 64) qs[t] = Qb[(size_t)i * FF + t];
        else        ks[t - 64] = Kb[(size_t)i * FF + (t - 64)];
        __syncthreads();                              // qs/ks/Kss valid
        float vd = Vb[(size_t)i * DD];
        float num = 0.f, den = 0.f;
        #pragma unroll
        for (int f = 0; f < 64; f++) {
            float kf = ks[f];
            kv[f] = fmaf(kf, vd, kv[f]);              // KV += k ⊗ v
            num   = fmaf(qs[f], kv[f], num);          // q · KV (inclusive)
            den   = fmaf(qs[f], Kss[f] + kf, den);    // q · (Ks + k) inclusive
        }
        Ob[(size_t)i * DD] = num / (den + 1e-6f);
        __syncthreads();                              // all reads of ks/Kss done
        if (t >= 64) Kss[t - 64] += ks[t - 64];       // same thread owns ks slot
    }
}

// ---------------- launch ------------------------------------------------------
extern "C" void kernel_launch(void* const* d_in, const int* in_sizes, int n_in,
                              void* d_out, int out_size) {
    const float* x    = (const float*)d_in[0];
    const float* ln1w = (const float*)d_in[1];
    const float* ln1b = (const float*)d_in[2];
    const float* qw   = (const float*)d_in[3];
    const float* qb   = (const float*)d_in[4];
    const float* kw   = (const float*)d_in[5];
    const float* kb   = (const float*)d_in[6];
    const float* vw   = (const float*)d_in[7];
    const float* vb   = (const float*)d_in[8];
    const float* ow   = (const float*)d_in[9];
    const float* ob   = (const float*)d_in[10];
    const float* ln2w = (const float*)d_in[11];
    const float* ln2b = (const float*)d_in[12];
    const float* f1w  = (const float*)d_in[13];
    const float* f1b  = (const float*)d_in[14];
    const float* f2w  = (const float*)d_in[15];
    const float* f2b  = (const float*)d_in[16];
    float* out = (float*)d_out;

    float *xn, *q, *k, *v, *attn, *y1, *h, *hf;
    cudaGetSymbolAddress((void**)&xn,   g_xn);
    cudaGetSymbolAddress((void**)&q,    g_q);
    cudaGetSymbolAddress((void**)&k,    g_k);
    cudaGetSymbolAddress((void**)&v,    g_v);
    cudaGetSymbolAddress((void**)&attn, g_attn);
    cudaGetSymbolAddress((void**)&y1,   g_y1);
    cudaGetSymbolAddress((void**)&h,    g_h);
    cudaGetSymbolAddress((void**)&hf,   g_hf);

    // 1. x_norm = LN1(x)
    ln_kernel<<<MROWS, 256>>>(x, ln1w, ln1b, xn);
    // 2. Q = elu(xn @ qw^T + qb)+1 ; K likewise
    gemm_tn<1><<<dim3(1, MROWS/64), 256>>>(xn, qw, qb, nullptr, q, MROWS, FF, DD);
    gemm_tn<1><<<dim3(1, MROWS/64), 256>>>(xn, kw, kb, nullptr, k, MROWS, FF, DD);
    // 3. V = xn @ vw^T + vb
    gemm_tn<0><<<dim3(DD/64, MROWS/64), 256>>>(xn, vw, vb, nullptr, v, MROWS, DD, DD);
    // 4. causal linear attention
    attn_scan<<<dim3(DD/128, BB), 128>>>(q, k, v, attn);
    // 5. y1 = x + attn @ ow^T + ob
    gemm_tn<3><<<dim3(DD/64, MROWS/64), 256>>>(attn, ow, ob, x, y1, MROWS, DD, DD);
    // 6. h = LN2(y1)
    ln_kernel<<<MROWS, 256>>>(y1, ln2w, ln2b, h);
    // 7. hf = gelu(h @ f1w^T + f1b)
    gemm_tn<2><<<dim3(HID/64, MROWS/64), 256>>>(h, f1w, f1b, nullptr, hf, MROWS, HID, DD);
    // 8. out = y1 + hf @ f2w^T + f2b
    gemm_tn<3><<<dim3(DD/64, MROWS/64), 256>>>(hf, f2w, f2b, y1, out, MROWS, DD, HID);
}

// round 10
// speedup vs baseline: 1.0021x; 1.0021x over previous
#include <cuda_runtime.h>
#include <math.h>

#define BB 4
#define NN 4096
#define DD 1024
#define FF 64
#define MROWS (BB*NN)      // 16384
#define HID (4*DD)         // 4096

// ---------------- scratch (static __device__ — no allocation allowed) -------
__device__ float g_xn[(size_t)MROWS*DD];
__device__ float g_q [(size_t)MROWS*FF];
__device__ float g_k [(size_t)MROWS*FF];
__device__ float g_v [(size_t)MROWS*DD];
__device__ float g_attn[(size_t)MROWS*DD];
__device__ float g_y1[(size_t)MROWS*DD];
__device__ float g_h [(size_t)MROWS*DD];
__device__ float g_hf[(size_t)MROWS*HID];

// ---------------- LayerNorm: one CTA per row of 1024 ------------------------
__global__ void ln_kernel(const float* __restrict__ x, const float* __restrict__ w,
                          const float* __restrict__ b, float* __restrict__ y) {
    int row = blockIdx.x;
    int t = threadIdx.x;                      // 256 threads, 1 float4 each
    const float4* xr = (const float4*)(x + (size_t)row * DD);
    float4 p = xr[t];
    float s  = p.x + p.y + p.z + p.w;
    float ss = p.x*p.x + p.y*p.y + p.z*p.z + p.w*p.w;
    #pragma unroll
    for (int o = 16; o; o >>= 1) {
        s  += __shfl_down_sync(0xffffffffu, s,  o);
        ss += __shfl_down_sync(0xffffffffu, ss, o);
    }
    __shared__ float rs[8], rss[8];
    int wid = t >> 5, lid = t & 31;
    if (lid == 0) { rs[wid] = s; rss[wid] = ss; }
    __syncthreads();
    float tot = 0.f, tot2 = 0.f;
    #pragma unroll
    for (int i = 0; i < 8; i++) { tot += rs[i]; tot2 += rss[i]; }
    float mu  = tot * (1.0f / DD);
    float var = tot2 * (1.0f / DD) - mu * mu;
    float inv = rsqrtf(var + 1e-5f);
    float4 wv = ((const float4*)w)[t];
    float4 bv = ((const float4*)b)[t];
    float4 o;
    o.x = (p.x - mu) * inv * wv.x + bv.x;
    o.y = (p.y - mu) * inv * wv.y + bv.y;
    o.z = (p.z - mu) * inv * wv.z + bv.z;
    o.w = (p.w - mu) * inv * wv.w + bv.w;
    ((float4*)(y + (size_t)row * DD))[t] = o;
}

// ---------------- GEMM: C[M,N] = A[M,K] @ W[N,K]^T + bias, with epilogue ----
// EPI: 0 = none, 1 = elu(x)+1, 2 = gelu exact, 3 = residual add
template<int EPI>
__global__ void gemm_tn(const float* __restrict__ A, const float* __restrict__ W,
                        const float* __restrict__ bias, const float* __restrict__ R,
                        float* __restrict__ C, int M, int Nout, int Kd) {
    __shared__ float As[16][68];   // [k][m], padded
    __shared__ float Ws[16][68];   // [k][n], padded
    int t  = threadIdx.x;
    int tx = t & 15, ty = t >> 4;
    int m0 = blockIdx.y * 64, n0 = blockIdx.x * 64;
    int lr = t >> 2;            // 0..63
    int lc = (t & 3) * 4;       // 0,4,8,12
    const float* Ag = A + (size_t)(m0 + lr) * Kd + lc;
    const float* Wg = W + (size_t)(n0 + lr) * Kd + lc;

    float acc[4][4];
    #pragma unroll
    for (int i = 0; i < 4; i++)
        #pragma unroll
        for (int j = 0; j < 4; j++) acc[i][j] = 0.f;

    for (int k0 = 0; k0 < Kd; k0 += 16) {
        float4 av = *(const float4*)(Ag + k0);
        float4 wv = *(const float4*)(Wg + k0);
        As[lc+0][lr] = av.x; As[lc+1][lr] = av.y;
        As[lc+2][lr] = av.z; As[lc+3][lr] = av.w;
        Ws[lc+0][lr] = wv.x; Ws[lc+1][lr] = wv.y;
        Ws[lc+2][lr] = wv.z; Ws[lc+3][lr] = wv.w;
        __syncthreads();
        #pragma unroll
        for (int kk = 0; kk < 16; kk++) {
            float4 a = *(const float4*)&As[kk][ty * 4];
            float4 b = *(const float4*)&Ws[kk][tx * 4];
            acc[0][0] += a.x*b.x; acc[0][1] += a.x*b.y; acc[0][2] += a.x*b.z; acc[0][3] += a.x*b.w;
            acc[1][0] += a.y*b.x; acc[1][1] += a.y*b.y; acc[1][2] += a.y*b.z; acc[1][3] += a.y*b.w;
            acc[2][0] += a.z*b.x; acc[2][1] += a.z*b.y; acc[2][2] += a.z*b.z; acc[2][3] += a.z*b.w;
            acc[3][0] += a.w*b.x; acc[3][1] += a.w*b.y; acc[3][2] += a.w*b.z; acc[3][3] += a.w*b.w;
        }
        __syncthreads();
    }

    #pragma unroll
    for (int i = 0; i < 4; i++) {
        int m = m0 + ty * 4 + i;
        #pragma unroll
        for (int j = 0; j < 4; j++) {
            int n = n0 + tx * 4 + j;
            float v = acc[i][j] + bias[n];
            if (EPI == 1) v = (v > 0.f) ? (v + 1.f) : expf(v);               // elu+1
            else if (EPI == 2) v = 0.5f * v * (1.f + erff(v * 0.70710678118f)); // gelu exact
            else if (EPI == 3) v += R[(size_t)m * Nout + n];                 // residual
            C[(size_t)m * Nout + n] = v;
        }
    }
}

// ---------------- causal linear attention scan -------------------------------
// grid: (D/128, B), 128 threads. Each thread owns one output dim d, holds
// KV[f=0..63][d] in registers. Exact replay of the reference recurrence.
__global__ void attn_scan(const float* __restrict__ Q, const float* __restrict__ K,
                          const float* __restrict__ V, float* __restrict__ O) {
    int b = blockIdx.y;
    int t = threadIdx.x;
    int d = blockIdx.x * 128 + t;
    __shared__ float qs[64], ks[64], Kss[64];
    if (t < 64) Kss[t] = 0.f;
    float kv[64];
    #pragma unroll
    for (int f = 0; f < 64; f++) kv[f] = 0.f;

    const float* Qb = Q + (size_t)b * NN * FF;
    const float* Kb = K + (size_t)b * NN * FF;
    const float* Vb = V + (size_t)b * NN * DD + d;
    float*       Ob = O + (size_t)b * NN * DD + d;

    for (int i = 0; i < NN; i++) {
        if (t < 64) qs[t] = Qb[(size_t)i * FF + t];
        else        ks[t - 64] = Kb[(size_t)i * FF + (t - 64)];
        __syncthreads();                              // qs/ks/Kss valid
        float vd = Vb[(size_t)i * DD];
        float num = 0.f, den = 0.f;
        #pragma unroll
        for (int f = 0; f < 64; f++) {
            float kf = ks[f];
            kv[f] = fmaf(kf, vd, kv[f]);              // KV += k ⊗ v
            num   = fmaf(qs[f], kv[f], num);          // q · KV (inclusive)
            den   = fmaf(qs[f], Kss[f] + kf, den);    // q · (Ks + k) inclusive
        }
        Ob[(size_t)i * DD] = num / (den + 1e-6f);
        __syncthreads();                              // all reads of ks/Kss done
        if (t >= 64) Kss[t - 64] += ks[t - 64];       // same thread owns ks slot
    }
}

// ---------------- launch ------------------------------------------------------
extern "C" void kernel_launch(void* const* d_in, const int* in_sizes, int n_in,
                              void* d_out, int out_size) {
    const float* x    = (const float*)d_in[0];
    const float* ln1w = (const float*)d_in[1];
    const float* ln1b = (const float*)d_in[2];
    const float* qw   = (const float*)d_in[3];
    const float* qb   = (const float*)d_in[4];
    const float* kw   = (const float*)d_in[5];
    const float* kb   = (const float*)d_in[6];
    const float* vw   = (const float*)d_in[7];
    const float* vb   = (const float*)d_in[8];
    const float* ow   = (const float*)d_in[9];
    const float* ob   = (const float*)d_in[10];
    const float* ln2w = (const float*)d_in[11];
    const float* ln2b = (const float*)d_in[12];
    const float* f1w  = (const float*)d_in[13];
    const float* f1b  = (const float*)d_in[14];
    const float* f2w  = (const float*)d_in[15];
    const float* f2b  = (const float*)d_in[16];
    float* out = (float*)d_out;

    float *xn, *q, *k, *v, *attn, *y1, *h, *hf;
    cudaGetSymbolAddress((void**)&xn,   g_xn);
    cudaGetSymbolAddress((void**)&q,    g_q);
    cudaGetSymbolAddress((void**)&k,    g_k);
    cudaGetSymbolAddress((void**)&v,    g_v);
    cudaGetSymbolAddress((void**)&attn, g_attn);
    cudaGetSymbolAddress((void**)&y1,   g_y1);
    cudaGetSymbolAddress((void**)&h,    g_h);
    cudaGetSymbolAddress((void**)&hf,   g_hf);

    // 1. x_norm = LN1(x)
    ln_kernel<<<MROWS, 256>>>(x, ln1w, ln1b, xn);
    // 2. Q = elu(xn @ qw^T + qb)+1 ; K likewise
    gemm_tn<1><<<dim3(1, MROWS/64), 256>>>(xn, qw, qb, nullptr, q, MROWS, FF, DD);
    gemm_tn<1><<<dim3(1, MROWS/64), 256>>>(xn, kw, kb, nullptr, k, MROWS, FF, DD);
    // 3. V = xn @ vw^T + vb
    gemm_tn<0><<<dim3(DD/64, MROWS/64), 256>>>(xn, vw, vb, nullptr, v, MROWS, DD, DD);
    // 4. causal linear attention
    attn_scan<<<dim3(DD/128, BB), 128>>>(q, k, v, attn);
    // 5. y1 = x + attn @ ow^T + ob
    gemm_tn<3><<<dim3(DD/64, MROWS/64), 256>>>(attn, ow, ob, x, y1, MROWS, DD, DD);
    // 6. h = LN2(y1)
    ln_kernel<<<MROWS, 256>>>(y1, ln2w, ln2b, h);
    // 7. hf = gelu(h @ f1w^T + f1b)
    gemm_tn<2><<<dim3(HID/64, MROWS/64), 256>>>(h, f1w, f1b, nullptr, hf, MROWS, HID, DD);
    // 8. out = y1 + hf @ f2w^T + f2b
    gemm_tn<3><<<dim3(DD/64, MROWS/64), 256>>>(hf, f2w, f2b, y1, out, MROWS, DD, HID);
}